// round 2
// baseline (speedup 1.0000x reference)
#include <cuda_runtime.h>
#include <cstdint>

#define NN 500
#define GG 128
#define HH 200
#define WW 304
#define HWPX (HH * WW)          // 60800
#define WORDS 1900              // HWPX / 32, exact
#define WSTRIDE 1920            // padded row stride (u32 words), 16B-multiple
#define MAXPAIRS (NN * (NN - 1) / 2)   // 124750
#define MASK_THR 0.005f
#define SIGMA 2.0f
#define NMS_BLOCKS 152          // one CTA per SM -> all co-resident, safe grid barrier
#define NMS_THREADS 256

// ---- device scratch (no allocations allowed) ----
__device__ __align__(16) unsigned int g_bits[NN * WSTRIDE]; // packed hard masks
__device__ int   g_area[NN];      // sum_masks (popcount)
__device__ float g_scores[NN];    // cate_scores * seg_score
__device__ float g_comp[NN];      // comp_iou (column max)
__device__ float g_coef[NN];      // running min of decay terms
__device__ int   g_npairs;
__device__ unsigned int g_pair_ij[MAXPAIRS];
__device__ float g_pair_d[MAXPAIRS];
__device__ volatile unsigned int g_bar;   // grid barrier counter (reset by decode)

// ============================================================
// Kernel A: decode masks, pack bits, compute rescored scores
// ============================================================
__global__ __launch_bounds__(256) void decode_kernel(
    const float* __restrict__ cate_scores,
    const float* __restrict__ segx,
    const float* __restrict__ segy,
    const int* __restrict__ x_inds,
    const int* __restrict__ y_inds)
{
    const int n = blockIdx.x;
    const int tid = threadIdx.x;

    const int xi = x_inds[n];
    const int yi = y_inds[n];
    const float4* __restrict__ rx = reinterpret_cast<const float4*>(segx + (size_t)xi * HWPX);
    const float4* __restrict__ ry = reinterpret_cast<const float4*>(segy + (size_t)yi * HWPX);

    int   area = 0;
    float ssum = 0.0f;

    // word w covers pixels [32w, 32w+32) = float4 indices [8w, 8w+8)
    for (int w = tid; w < WORDS; w += 256) {
        unsigned int bits = 0;
        const int f4 = w * 8;
#pragma unroll
        for (int q = 0; q < 8; q++) {
            float4 a = rx[f4 + q];
            float4 b = ry[f4 + q];
            float s0 = a.x * b.x;
            float s1 = a.y * b.y;
            float s2 = a.z * b.z;
            float s3 = a.w * b.w;
            if (s0 > MASK_THR) { bits |= 1u << (q * 4 + 0); ssum += s0; }
            if (s1 > MASK_THR) { bits |= 1u << (q * 4 + 1); ssum += s1; }
            if (s2 > MASK_THR) { bits |= 1u << (q * 4 + 2); ssum += s2; }
            if (s3 > MASK_THR) { bits |= 1u << (q * 4 + 3); ssum += s3; }
        }
        g_bits[n * WSTRIDE + w] = bits;
        area += __popc(bits);
    }
    // zero the pad words (so uint4 reads in the pair phase see zeros)
    if (tid < WSTRIDE - WORDS)
        g_bits[n * WSTRIDE + WORDS + tid] = 0u;

    // block reduction (8 warps)
    __shared__ float s_sum[8];
    __shared__ int   s_area[8];
#pragma unroll
    for (int off = 16; off > 0; off >>= 1) {
        ssum += __shfl_down_sync(0xffffffffu, ssum, off);
        area += __shfl_down_sync(0xffffffffu, area, off);
    }
    if ((tid & 31) == 0) { s_sum[tid >> 5] = ssum; s_area[tid >> 5] = area; }
    __syncthreads();
    if (tid == 0) {
        float tsum = 0.0f; int tarea = 0;
#pragma unroll
        for (int k = 0; k < 8; k++) { tsum += s_sum[k]; tarea += s_area[k]; }
        g_area[n] = tarea;
        float seg_score = tsum / fmaxf((float)tarea, 1.0f);
        g_scores[n] = cate_scores[n] * seg_score;
        g_comp[n] = 0.0f;
        g_coef[n] = 1.0f;
        if (n == 0) { g_npairs = 0; g_bar = 0u; }
    }
}

// ============================================================
// Grid barrier: all NMS_BLOCKS CTAs are co-resident (1/SM).
// ============================================================
__device__ __forceinline__ void grid_barrier(unsigned int target)
{
    __syncthreads();
    __threadfence();                   // release: publish phase writes
    if (threadIdx.x == 0) {
        atomicAdd((unsigned int*)&g_bar, 1u);
        while (g_bar < target) __nanosleep(64);
    }
    __syncthreads();
    __threadfence();                   // acquire side
}

// ============================================================
// Kernel B (persistent): pair popc -> barrier -> decay -> barrier -> final
// ============================================================
__global__ __launch_bounds__(NMS_THREADS) void nms_kernel(
    const int* __restrict__ labels,
    float* __restrict__ out)
{
    __shared__ int s_lab[NN];
    const int tid = threadIdx.x;
    const int gtid = blockIdx.x * NMS_THREADS + tid;
    const int lane = tid & 31;
    const int gwarp = gtid >> 5;
    const int NWARPS = NMS_BLOCKS * (NMS_THREADS / 32);

    for (int k = tid; k < NN; k += NMS_THREADS) s_lab[k] = labels[k];
    __syncthreads();

    // ---- Phase 1: same-label pair intersections (one warp per candidate) ----
    for (int p = gwarp; p < NN * NN; p += NWARPS) {
        const int i = p / NN;
        const int j = p - i * NN;
        if (j <= i) continue;
        if (s_lab[i] != s_lab[j]) continue;

        const uint4* __restrict__ bi = reinterpret_cast<const uint4*>(g_bits + i * WSTRIDE);
        const uint4* __restrict__ bj = reinterpret_cast<const uint4*>(g_bits + j * WSTRIDE);

        int inter = 0;
#pragma unroll 5
        for (int w = lane; w < WSTRIDE / 4; w += 32) {   // 15 iterations
            uint4 a = bi[w];
            uint4 b = bj[w];
            inter += __popc(a.x & b.x) + __popc(a.y & b.y)
                   + __popc(a.z & b.z) + __popc(a.w & b.w);
        }
#pragma unroll
        for (int off = 16; off > 0; off >>= 1)
            inter += __shfl_down_sync(0xffffffffu, inter, off);

        if (lane == 0) {
            float uni = (float)(g_area[i] + g_area[j] - inter);
            float iou = (float)inter / fmaxf(uni, 1e-6f);
            atomicMax(reinterpret_cast<int*>(&g_comp[j]), __float_as_int(iou));
            int pos = atomicAdd(&g_npairs, 1);
            g_pair_ij[pos] = ((unsigned)i << 16) | (unsigned)j;
            g_pair_d[pos] = iou;
        }
    }

    grid_barrier(NMS_BLOCKS);

    // ---- Phase 2: decay terms -> min into coef[j] ----
    const int np = g_npairs;
    for (int p = gtid; p < np; p += NMS_BLOCKS * NMS_THREADS) {
        unsigned ij = g_pair_ij[p];
        int i = (int)(ij >> 16);
        int j = (int)(ij & 0xffffu);
        float d = g_pair_d[p];
        float c = g_comp[i];
        // exp(-sigma*d^2)/exp(-sigma*c^2) = exp(sigma*(c^2 - d^2)) > 0
        float term = __expf(SIGMA * (c * c - d * d));
        atomicMin(reinterpret_cast<int*>(&g_coef[j]), __float_as_int(term));
    }

    grid_barrier(2 * NMS_BLOCKS);

    // ---- Phase 3: final scores ----
    if (gtid < NN) {
        float coef = fminf(g_coef[gtid], 1.0f);  // rows with zero decay_iou contribute exactly 1
        out[gtid] = g_scores[gtid] * coef;
    }
}

extern "C" void kernel_launch(void* const* d_in, const int* in_sizes, int n_in,
                              void* d_out, int out_size)
{
    const float* cate_scores = (const float*)d_in[0];
    const float* segx        = (const float*)d_in[1];
    const float* segy        = (const float*)d_in[2];
    const int*   labels      = (const int*)d_in[3];
    const int*   x_inds      = (const int*)d_in[4];
    const int*   y_inds      = (const int*)d_in[5];
    float* out = (float*)d_out;

    decode_kernel<<<NN, 256>>>(cate_scores, segx, segy, x_inds, y_inds);
    nms_kernel<<<NMS_BLOCKS, NMS_THREADS>>>(labels, out);
}

// round 3
// speedup vs baseline: 1.4946x; 1.4946x over previous
#include <cuda_runtime.h>
#include <cstdint>

#define NN 500
#define GG 128
#define HH 200
#define WW 304
#define HWPX (HH * WW)          // 60800
#define WORDS 1900              // HWPX / 32, exact
#define WSTRIDE 1920            // padded row stride (u32 words), 16B multiple
#define HALFW 950               // words per decode CTA (2 CTAs per mask)
#define MAXPAIRS (NN * (NN - 1) / 2)   // 124750
#define MASK_THR 0.005f
#define SIGMA 2.0f

// ---- device scratch (zero-initialized at load; final_kernel re-zeroes
//      the accumulators each replay so the invariant holds across replays) ----
__device__ __align__(16) unsigned int g_bits[NN * WSTRIDE]; // packed hard masks
__device__ int   g_area[NN];      // accumulated popcount (zero at kernel_launch entry)
__device__ float g_ssum[NN];      // accumulated soft*hard sum (zero at entry)
__device__ float g_comp[NN];      // comp_iou (init in pairbuild)
__device__ float g_coef[NN];      // running min decay term (init in pairbuild)
__device__ int   g_npairs;        // zero at entry
__device__ unsigned int g_pair_ij[MAXPAIRS];
__device__ float g_pair_d[MAXPAIRS];

// ============================================================
// Kernel 1: decode. 2 CTAs per mask (blockIdx.x = mask*2 + half).
// ============================================================
__global__ __launch_bounds__(256) void decode_kernel(
    const float* __restrict__ segx,
    const float* __restrict__ segy,
    const int* __restrict__ x_inds,
    const int* __restrict__ y_inds)
{
    const int n    = blockIdx.x >> 1;
    const int half = blockIdx.x & 1;
    const int tid  = threadIdx.x;

    const int xi = x_inds[n];
    const int yi = y_inds[n];
    const float4* __restrict__ rx = reinterpret_cast<const float4*>(segx + (size_t)xi * HWPX);
    const float4* __restrict__ ry = reinterpret_cast<const float4*>(segy + (size_t)yi * HWPX);

    const int w0 = half * HALFW;
    const int w1 = w0 + HALFW;

    int   area = 0;
    float ssum = 0.0f;

    for (int w = w0 + tid; w < w1; w += 256) {
        unsigned int bits = 0;
        const int f4 = w * 8;
#pragma unroll
        for (int q = 0; q < 8; q++) {
            float4 a = rx[f4 + q];
            float4 b = ry[f4 + q];
            float s0 = a.x * b.x;
            float s1 = a.y * b.y;
            float s2 = a.z * b.z;
            float s3 = a.w * b.w;
            if (s0 > MASK_THR) { bits |= 1u << (q * 4 + 0); ssum += s0; }
            if (s1 > MASK_THR) { bits |= 1u << (q * 4 + 1); ssum += s1; }
            if (s2 > MASK_THR) { bits |= 1u << (q * 4 + 2); ssum += s2; }
            if (s3 > MASK_THR) { bits |= 1u << (q * 4 + 3); ssum += s3; }
        }
        g_bits[n * WSTRIDE + w] = bits;
        area += __popc(bits);
    }
    // zero pad words [1900,1920) so uint4 reads in popc see zeros
    if (half == 1 && tid < WSTRIDE - WORDS)
        g_bits[n * WSTRIDE + WORDS + tid] = 0u;

    // block reduction (8 warps)
    __shared__ float s_sum[8];
    __shared__ int   s_area[8];
#pragma unroll
    for (int off = 16; off > 0; off >>= 1) {
        ssum += __shfl_down_sync(0xffffffffu, ssum, off);
        area += __shfl_down_sync(0xffffffffu, area, off);
    }
    if ((tid & 31) == 0) { s_sum[tid >> 5] = ssum; s_area[tid >> 5] = area; }
    __syncthreads();
    if (tid == 0) {
        float tsum = 0.0f; int tarea = 0;
#pragma unroll
        for (int k = 0; k < 8; k++) { tsum += s_sum[k]; tarea += s_area[k]; }
        // exactly 2 contributions per mask -> fp-add commutative -> deterministic
        atomicAdd(&g_ssum[n], tsum);
        atomicAdd(&g_area[n], tarea);
    }
}

// ============================================================
// Kernel 2: build compact same-label pair list + init comp/coef
// ============================================================
__global__ __launch_bounds__(256) void pairbuild_kernel(const int* __restrict__ labels)
{
    const int i = blockIdx.x;
    const int tid = threadIdx.x;
    const int lab = labels[i];
    if (tid == 0) { g_comp[i] = 0.0f; g_coef[i] = 1.0f; }
    for (int j = i + 1 + tid; j < NN; j += 256) {
        if (labels[j] == lab) {
            int pos = atomicAdd(&g_npairs, 1);
            g_pair_ij[pos] = ((unsigned)i << 16) | (unsigned)j;
        }
    }
}

// ============================================================
// Kernel 3: pair popcount intersections (one warp per pair)
// ============================================================
__global__ __launch_bounds__(256) void popc_kernel()
{
    const int lane  = threadIdx.x & 31;
    const int gwarp = (blockIdx.x * 256 + threadIdx.x) >> 5;
    const int NW    = gridDim.x * 8;
    const int np    = g_npairs;

    for (int p = gwarp; p < np; p += NW) {
        const unsigned ij = g_pair_ij[p];
        const int i = (int)(ij >> 16);
        const int j = (int)(ij & 0xffffu);

        const uint4* __restrict__ bi = reinterpret_cast<const uint4*>(g_bits + i * WSTRIDE);
        const uint4* __restrict__ bj = reinterpret_cast<const uint4*>(g_bits + j * WSTRIDE);

        int inter = 0;
#pragma unroll 5
        for (int w = lane; w < WSTRIDE / 4; w += 32) {   // 15 iterations
            uint4 a = bi[w];
            uint4 b = bj[w];
            inter += __popc(a.x & b.x) + __popc(a.y & b.y)
                   + __popc(a.z & b.z) + __popc(a.w & b.w);
        }
#pragma unroll
        for (int off = 16; off > 0; off >>= 1)
            inter += __shfl_down_sync(0xffffffffu, inter, off);

        if (lane == 0) {
            float uni = (float)(g_area[i] + g_area[j] - inter);
            float iou = (float)inter / fmaxf(uni, 1e-6f);
            g_pair_d[p] = iou;
            // iou >= 0: int ordering == float ordering
            atomicMax(reinterpret_cast<int*>(&g_comp[j]), __float_as_int(iou));
        }
    }
}

// ============================================================
// Kernel 4: decay terms -> min into coef[j]
// ============================================================
__global__ __launch_bounds__(256) void decay_kernel()
{
    const int np = g_npairs;
    for (int p = blockIdx.x * 256 + threadIdx.x; p < np; p += gridDim.x * 256) {
        unsigned ij = g_pair_ij[p];
        int i = (int)(ij >> 16);
        int j = (int)(ij & 0xffffu);
        float d = g_pair_d[p];
        float c = g_comp[i];
        // exp(-sigma*d^2)/exp(-sigma*c^2) = exp(sigma*(c^2-d^2)) > 0
        float term = __expf(SIGMA * (c * c - d * d));
        atomicMin(reinterpret_cast<int*>(&g_coef[j]), __float_as_int(term));
    }
}

// ============================================================
// Kernel 5: final scores + reset accumulators for next replay
// ============================================================
__global__ void final_kernel(const float* __restrict__ cate_scores,
                             float* __restrict__ out)
{
    const int n = blockIdx.x * 256 + threadIdx.x;
    if (n < NN) {
        float area = (float)g_area[n];
        float seg_score = g_ssum[n] / fmaxf(area, 1.0f);
        float score = cate_scores[n] * seg_score;
        float coef = fminf(g_coef[n], 1.0f);  // zero-decay rows contribute exactly 1
        out[n] = score * coef;
        // reset accumulators so next replay sees zeros
        g_area[n] = 0;
        g_ssum[n] = 0.0f;
        if (n == 0) g_npairs = 0;
    }
}

extern "C" void kernel_launch(void* const* d_in, const int* in_sizes, int n_in,
                              void* d_out, int out_size)
{
    const float* cate_scores = (const float*)d_in[0];
    const float* segx        = (const float*)d_in[1];
    const float* segy        = (const float*)d_in[2];
    const int*   labels      = (const int*)d_in[3];
    const int*   x_inds      = (const int*)d_in[4];
    const int*   y_inds      = (const int*)d_in[5];
    float* out = (float*)d_out;

    decode_kernel<<<2 * NN, 256>>>(segx, segy, x_inds, y_inds);
    pairbuild_kernel<<<NN, 256>>>(labels);
    popc_kernel<<<208, 256>>>();
    decay_kernel<<<16, 256>>>();
    final_kernel<<<2, 256>>>(cate_scores, out);
}